// round 5
// baseline (speedup 1.0000x reference)
#include <cuda_runtime.h>
#include <cuda_bf16.h>
#include <cstdint>

#define EPSF 1e-6f
#define L2E  1.4426950408889634f

static constexpr int I_DIM = 16384;
static constexpr int JK_DIM = 8192;
static constexpr int D_DIM = 128;

// ---------------- scratch (static __device__, no allocs) ----------------
__device__ __nv_bfloat16 g_lb[I_DIM * D_DIM];
__device__ __nv_bfloat16 g_rb[JK_DIM * D_DIM];
__device__ __nv_bfloat16 g_ub[JK_DIM * D_DIM];
__device__ float  g_col_rl[I_DIM];
__device__ float  g_col_ul[I_DIM];
__device__ float  g_nl[I_DIM];     // ||l||^2 - 2*eps*sum(l): folds A-side eps into GEMM
__device__ float  g_nar[JK_DIM];   // ||r+eps||^2
__device__ float  g_nau[JK_DIM];   // ||u+eps||^2
__device__ double g_edge_sum;

// ---------------- helpers ----------------
__device__ __forceinline__ uint32_t smem_u32(const void* p) {
    uint32_t a;
    asm("{ .reg .u64 t; cvta.to.shared.u64 t, %1; cvt.u32.u64 %0, t; }" : "=r"(a) : "l"(p));
    return a;
}
__device__ __forceinline__ float sqrt_approx(float x) {
    float r; asm("sqrt.approx.f32 %0, %1;" : "=f"(r) : "f"(x)); return r;
}
__device__ __forceinline__ float rsqrt_approx(float x) {
    float r; asm("rsqrt.approx.f32 %0, %1;" : "=f"(r) : "f"(x)); return r;
}
// 2^t on the FMA pipe: magic-constant round + degree-5 poly on f in [-0.5,0.5]
__device__ __forceinline__ float fast_ex2(float t) {
    t = fmaxf(t, -120.0f);
    float z = t + 12582912.0f;
    int   nb = __float_as_int(z) - 0x4B400000;
    float f = t - (z - 12582912.0f);
    float s = __int_as_float((nb + 127) << 23);
    float p = 1.3333558e-3f;
    p = fmaf(p, f, 9.6181291e-3f);
    p = fmaf(p, f, 5.5504109e-2f);
    p = fmaf(p, f, 2.4022651e-1f);
    p = fmaf(p, f, 6.9314718e-1f);
    p = fmaf(p, f, 1.0f);
    return s * p;
}
__device__ __forceinline__ float4 ld_bf16x4(const __nv_bfloat16* p) {
    uint2 v = *(const uint2*)p;
    __nv_bfloat162 lo = *(__nv_bfloat162*)&v.x;
    __nv_bfloat162 hi = *(__nv_bfloat162*)&v.y;
    float2 f0 = __bfloat1622float2(lo), f1 = __bfloat1622float2(hi);
    return make_float4(f0.x, f0.y, f1.x, f1.y);
}
__device__ __forceinline__ void ldsm_x4(uint32_t& r0, uint32_t& r1, uint32_t& r2, uint32_t& r3,
                                        uint32_t addr) {
    asm volatile("ldmatrix.sync.aligned.m8n8.x4.shared.b16 {%0,%1,%2,%3}, [%4];"
                 : "=r"(r0), "=r"(r1), "=r"(r2), "=r"(r3) : "r"(addr));
}
__device__ __forceinline__ void mma_16816(float* c, const uint32_t* a, const uint32_t* b) {
    asm volatile(
        "mma.sync.aligned.m16n8k16.row.col.f32.bf16.bf16.f32 "
        "{%0,%1,%2,%3}, {%4,%5,%6,%7}, {%8,%9}, {%0,%1,%2,%3};"
        : "+f"(c[0]), "+f"(c[1]), "+f"(c[2]), "+f"(c[3])
        : "r"(a[0]), "r"(a[1]), "r"(a[2]), "r"(a[3]), "r"(b[0]), "r"(b[1]));
}

// ---------------- init ----------------
__global__ void init_kernel() {
    int t = blockIdx.x * blockDim.x + threadIdx.x;
    if (t < I_DIM) { g_col_rl[t] = 0.0f; g_col_ul[t] = 0.0f; }
    if (t == 0) g_edge_sum = 0.0;
}

// ---------------- convert fp32 -> bf16 + norms (warp per row) ----------------
__global__ void convert_kernel(const float* __restrict__ l,
                               const float* __restrict__ r,
                               const float* __restrict__ u) {
    int warp = (blockIdx.x * blockDim.x + threadIdx.x) >> 5;
    int lane = threadIdx.x & 31;
    int total = I_DIM + 2 * JK_DIM;
    if (warp >= total) return;
    const float* src; __nv_bfloat16* dstb; float* dstn; int row; bool isL;
    if (warp < I_DIM)               { src = l; dstb = g_lb; dstn = g_nl;  row = warp;                 isL = true;  }
    else if (warp < I_DIM + JK_DIM) { src = r; dstb = g_rb; dstn = g_nar; row = warp - I_DIM;          isL = false; }
    else                            { src = u; dstb = g_ub; dstn = g_nau; row = warp - I_DIM - JK_DIM; isL = false; }
    float4 v = __ldg((const float4*)(src + (size_t)row * D_DIM) + lane);
    __nv_bfloat162 b0 = __float22bfloat162_rn(make_float2(v.x, v.y));
    __nv_bfloat162 b1 = __float22bfloat162_rn(make_float2(v.z, v.w));
    uint2 pk; pk.x = *(uint32_t*)&b0; pk.y = *(uint32_t*)&b1;
    *((uint2*)(dstb + (size_t)row * D_DIM) + lane) = pk;
    float s, t;
    if (isL) {
        s = v.x * v.x + v.y * v.y + v.z * v.z + v.w * v.w;
        t = v.x + v.y + v.z + v.w;
    } else {
        float a = v.x + EPSF, b = v.y + EPSF, c = v.z + EPSF, d = v.w + EPSF;
        s = a * a + b * b + c * c + d * d;
        t = 0.0f;
    }
    #pragma unroll
    for (int o = 16; o; o >>= 1) {
        s += __shfl_xor_sync(0xffffffffu, s, o);
        t += __shfl_xor_sync(0xffffffffu, t, o);
    }
    if (lane == 0) dstn[row] = isL ? (s - 2.0f * EPSF * t) : s;
}

// ---------------- fused kernel: rate GEMM blocks + interleaved edge blocks ----
// Grid: groups of 9 blocks -> 8 rate + 1 edge. 16384 rate blocks (8192 rl +
// 8192 ul), 2048 edge blocks interleaved so LTS-bound edge work overlaps the
// tensor/FMA-bound rate work within each wave.
#define TILE_ROW_B 256
#define A_OFF 0
#define B_OFF (128 * TILE_ROW_B)            // 32768
#define RATE_SMEM 65536
#define EDGE_BLOCKS 2048

__device__ __forceinline__ void rate_path(char* dsmem, float* nl_s, int ridx,
                                          const float* __restrict__ nu,
                                          const float* __restrict__ tau) {
    int which = ridx >> 13;                 // 0: rl, 1: ul
    int r2 = ridx & 8191;
    int ib = (r2 & 127) * 128;              // 128 i-blocks
    int jb = (r2 >> 7) * 128;               // 64 j-blocks

    const __nv_bfloat16* Ab = which ? g_ub : g_rb;
    const float* na   = which ? g_nau : g_nar;
    const float* bias = which ? tau : nu;
    float*       col  = which ? g_col_ul : g_col_rl;

    int tid = threadIdx.x;
    int wid = tid >> 5;
    int lane = tid & 31;
    int wj = wid >> 1;          // 0..3 -> j offset wj*32
    int wi = wid & 1;           // 0..1 -> i offset wi*64

    uint32_t sb = smem_u32(dsmem);

    // ---- load tiles: each 128 rows x 16 chunks(16B); XOR swizzle chunk^(row&7)
    #pragma unroll
    for (int t = 0; t < 8; t++) {
        int idx = tid + t * 256;
        int row = idx >> 4, c = idx & 15;
        int sc = c ^ (row & 7);
        uint4 va = __ldg((const uint4*)(Ab + (size_t)(jb + row) * D_DIM) + c);
        *(uint4*)(dsmem + A_OFF + row * TILE_ROW_B + sc * 16) = va;
        uint4 vb = __ldg((const uint4*)(g_lb + (size_t)(ib + row) * D_DIM) + c);
        *(uint4*)(dsmem + B_OFF + row * TILE_ROW_B + sc * 16) = vb;
    }
    if (tid < 128) nl_s[tid] = g_nl[ib + tid];
    __syncthreads();

    // ---- mainloop: 8 k-steps of m16n8k16 ----
    float acc[2][8][4];
    #pragma unroll
    for (int mt = 0; mt < 2; mt++)
        #pragma unroll
        for (int nt = 0; nt < 8; nt++)
            #pragma unroll
            for (int e = 0; e < 4; e++) acc[mt][nt][e] = 0.0f;

    int a_row0 = wj * 32 + (lane & 15);
    int a_csel = lane >> 4;                    // 0/1
    // B x4: pair p covers nt=2p,2p+1. row = wi*64 + p*16 + (lane>>4)*8 + (lane&7)
    int b_row0 = wi * 64 + ((lane >> 4) << 3) + (lane & 7);
    int b_csel = (lane >> 3) & 1;

    #pragma unroll
    for (int ks = 0; ks < 8; ks++) {
        uint32_t a[2][4];
        #pragma unroll
        for (int mt = 0; mt < 2; mt++) {
            int row = a_row0 + mt * 16;
            int c = (ks * 2 + a_csel) ^ (row & 7);
            ldsm_x4(a[mt][0], a[mt][1], a[mt][2], a[mt][3],
                    sb + A_OFF + row * TILE_ROW_B + c * 16);
        }
        uint32_t b[8][2];
        #pragma unroll
        for (int p = 0; p < 4; p++) {
            int row = b_row0 + p * 16;
            int c = (ks * 2 + b_csel) ^ (row & 7);
            ldsm_x4(b[2 * p][0], b[2 * p][1], b[2 * p + 1][0], b[2 * p + 1][1],
                    sb + B_OFF + row * TILE_ROW_B + c * 16);
        }
        #pragma unroll
        for (int mt = 0; mt < 2; mt++)
            #pragma unroll
            for (int nt = 0; nt < 8; nt++)
                mma_16816(acc[mt][nt], a[mt], b[nt]);
    }

    // ---- epilogue: exp(bias_j - eps - sqrt(d2)); in-register column reduce ----
    int g = lane >> 2;                 // row group (0..7)
    int tq = lane & 3;                 // col quad
    float c1j[4], c0j[4];
    #pragma unroll
    for (int mt = 0; mt < 2; mt++)
        #pragma unroll
        for (int h = 0; h < 2; h++) {
            int jr = wj * 32 + mt * 16 + h * 8 + g;
            c1j[mt * 2 + h] = na[jb + jr];
            c0j[mt * 2 + h] = (__ldg(&bias[jb + jr]) - EPSF) * L2E;
        }

    float colacc[16];
    #pragma unroll
    for (int c = 0; c < 16; c++) colacc[c] = 0.0f;

    #pragma unroll
    for (int nt = 0; nt < 8; nt++) {
        int i0 = wi * 64 + nt * 8 + tq * 2;
        float n0 = nl_s[i0], n1 = nl_s[i0 + 1];
        #pragma unroll
        for (int mt = 0; mt < 2; mt++) {
            #pragma unroll
            for (int h = 0; h < 2; h++) {
                float na_j = c1j[mt * 2 + h], b_j = c0j[mt * 2 + h];
                float d20 = fmaf(-2.0f, acc[mt][nt][h * 2 + 0], na_j + n0);
                float d21 = fmaf(-2.0f, acc[mt][nt][h * 2 + 1], na_j + n1);
                d20 = fmaxf(d20, 0.0f);
                d21 = fmaxf(d21, 0.0f);
                colacc[nt * 2 + 0] += fast_ex2(fmaf(sqrt_approx(d20), -L2E, b_j));
                colacc[nt * 2 + 1] += fast_ex2(fmaf(sqrt_approx(d21), -L2E, b_j));
            }
        }
    }
    // reduce over g (lane bits 2..4); lanes sharing tq combine
    #pragma unroll
    for (int c = 0; c < 16; c++) {
        colacc[c] += __shfl_xor_sync(0xffffffffu, colacc[c], 4);
        colacc[c] += __shfl_xor_sync(0xffffffffu, colacc[c], 8);
        colacc[c] += __shfl_xor_sync(0xffffffffu, colacc[c], 16);
    }
    if (lane < 4) {
        #pragma unroll
        for (int c = 0; c < 16; c++) {
            int ci = wi * 64 + (c >> 1) * 8 + lane * 2 + (c & 1);
            atomicAdd(&col[ib + ci], colacc[c]);
        }
    }
}

__device__ __forceinline__ void edge_path(int eb,
                                          const float* __restrict__ rho,
                                          const float* __restrict__ nu,
                                          const float* __restrict__ tau,
                                          const float* __restrict__ w,
                                          const int* __restrict__ si,
                                          const int* __restrict__ sj,
                                          const int* __restrict__ sk, int E) {
    int lane = threadIdx.x & 31;
    int warp = eb * 8 + (threadIdx.x >> 5);
    const int nwarps = EDGE_BLOCKS * 8;
    float local = 0.0f;
    for (int e = warp; e < E; e += nwarps) {
        int i = __ldg(&si[e]);
        int j = __ldg(&sj[e]);
        int k = __ldg(&sk[e]);
        float4 lv = ld_bf16x4(g_lb + (size_t)i * D_DIM + lane * 4);
        float4 rv = ld_bf16x4(g_rb + (size_t)j * D_DIM + lane * 4);
        float4 uv = ld_bf16x4(g_ub + (size_t)k * D_DIM + lane * 4);
        float ax = lv.x - rv.x + EPSF, ay = lv.y - rv.y + EPSF;
        float az = lv.z - rv.z + EPSF, aw = lv.w - rv.w + EPSF;
        float bx = lv.x - uv.x + EPSF, by = lv.y - uv.y + EPSF;
        float bz = lv.z - uv.z + EPSF, bw = lv.w - uv.w + EPSF;
        float s1 = ax * ax + ay * ay + az * az + aw * aw;
        float s2 = bx * bx + by * by + bz * bz + bw * bw;
        #pragma unroll
        for (int o = 16; o; o >>= 1) {
            s1 += __shfl_xor_sync(0xffffffffu, s1, o);
            s2 += __shfl_xor_sync(0xffffffffu, s2, o);
        }
        if (lane == 0) {
            s1 = fmaxf(s1, 1e-12f);
            s2 = fmaxf(s2, 1e-12f);
            float d1 = s1 * rsqrt_approx(s1);
            float d2 = s2 * rsqrt_approx(s2);
            local += __ldg(&w[e]) * (__ldg(&rho[i]) + __ldg(&nu[j]) + __ldg(&tau[k]) - d1 - d2);
        }
    }
    if (lane == 0) atomicAdd(&g_edge_sum, (double)local);
}

__global__ __launch_bounds__(256, 2)
void fused_kernel(const float* __restrict__ nu, const float* __restrict__ tau,
                  const float* __restrict__ rho, const float* __restrict__ w,
                  const int* __restrict__ si, const int* __restrict__ sj,
                  const int* __restrict__ sk, int E) {
    extern __shared__ char dsmem[];
    __shared__ float nl_s[128];
    int bx = blockIdx.x;
    int grp = bx / 9, rem = bx - grp * 9;
    if (rem == 8) {
        edge_path(grp, rho, nu, tau, w, si, sj, sk, E);
    } else {
        rate_path(dsmem, nl_s, grp * 8 + rem, nu, tau);
    }
}

// ---------------- final scalar ----------------
__global__ void final_kernel(const float* __restrict__ rho, float* __restrict__ out) {
    __shared__ double sm[256];
    int tid = threadIdx.x;
    double s = 0.0;
    for (int i = tid; i < I_DIM; i += 256)
        s += (double)g_col_rl[i] * (double)(__expf(rho[i]) * g_col_ul[i]);
    sm[tid] = s;
    __syncthreads();
    for (int o = 128; o; o >>= 1) {
        if (tid < o) sm[tid] += sm[tid + o];
        __syncthreads();
    }
    if (tid == 0) out[0] = (float)(g_edge_sum - sm[0]);
}

// ---------------- launch ----------------
extern "C" void kernel_launch(void* const* d_in, const int* in_sizes, int n_in,
                              void* d_out, int out_size) {
    const float* l   = (const float*)d_in[0];
    const float* r   = (const float*)d_in[1];
    const float* u   = (const float*)d_in[2];
    const float* rho = (const float*)d_in[3];
    const float* nu  = (const float*)d_in[4];
    const float* tau = (const float*)d_in[5];
    const float* w   = (const float*)d_in[6];
    const int*   si  = (const int*)d_in[7];
    const int*   sj  = (const int*)d_in[8];
    const int*   sk  = (const int*)d_in[9];
    int E = in_sizes[6];

    cudaFuncSetAttribute(fused_kernel, cudaFuncAttributeMaxDynamicSharedMemorySize, RATE_SMEM);

    init_kernel<<<64, 256>>>();
    int rows = I_DIM + 2 * JK_DIM;
    convert_kernel<<<(rows + 7) / 8, 256>>>(l, r, u);

    // 16384 rate blocks + 2048 edge blocks, interleaved 8:1
    fused_kernel<<<18432, 256, RATE_SMEM>>>(nu, tau, rho, w, si, sj, sk, E);

    final_kernel<<<1, 256>>>(rho, (float*)d_out);
}